// round 3
// baseline (speedup 1.0000x reference)
#include <cuda_runtime.h>
#include <math_constants.h>

#define FDIM 256
#define SGRAPHS 512
#define ROWS 8          // graphs per block in the GEMM kernel

__device__ float g_pool[SGRAPHS * FDIM];   // zero at load; empty segments stay 0
__device__ float g_gsum[SGRAPHS];

__device__ __forceinline__ int lowerb(const int* __restrict__ a, int n, int v) {
    int lo = 0, hi = n;
    while (lo < hi) { int m = (lo + hi) >> 1; if (a[m] < v) lo = m + 1; else hi = m; }
    return lo;
}

// Kernel 1: one block per graph. Single pass over x with online softmax-weighted
// feature accumulation. Writes normalized gate[N], g_pool[b][:], g_gsum[b].
__global__ __launch_bounds__(256) void pool_kernel(
    const float* __restrict__ x, const int* __restrict__ batch, int n_nodes,
    const float* __restrict__ Wg, const float* __restrict__ bg,
    float* __restrict__ gate)
{
    const int b   = blockIdx.x;
    const int tid = threadIdx.x;
    const int w   = tid >> 5, l = tid & 31;

    __shared__ int   s_b[2];
    __shared__ float s_m[8], s_s[8];
    __shared__ float s_acc[8][FDIM];

    if (tid == 0) {                      // one search, broadcast via smem
        s_b[0] = lowerb(batch, n_nodes, b);
        s_b[1] = lowerb(batch, n_nodes, b + 1);
    }
    __syncthreads();
    const int start = s_b[0], end = s_b[1];
    if (end == start) return;            // g_pool/g_gsum stay zero -> out row = 0

    const float4 wg0 = *(const float4*)(Wg + l * 8);
    const float4 wg1 = *(const float4*)(Wg + l * 8 + 4);
    const float  bgv = bg[0];

    // Online (max, sumexp, weighted-acc) per warp; one node per warp-iteration.
    float  m  = -CUDART_INF_F, ss = 0.f;
    float4 a0 = make_float4(0.f, 0.f, 0.f, 0.f);
    float4 a1 = make_float4(0.f, 0.f, 0.f, 0.f);

    for (int i = start + w; i < end; i += 8) {
        const float4* xr = (const float4*)(x + (size_t)i * FDIM);
        float4 v0 = xr[l * 2];
        float4 v1 = xr[l * 2 + 1];
        float d = v0.x*wg0.x + v0.y*wg0.y + v0.z*wg0.z + v0.w*wg0.w
                + v1.x*wg1.x + v1.y*wg1.y + v1.z*wg1.z + v1.w*wg1.w;
        #pragma unroll
        for (int o = 16; o; o >>= 1) d += __shfl_xor_sync(0xffffffffu, d, o);
        d += bgv;                        // every lane holds the full logit
        if (l == 0) gate[i] = d;         // stash raw logit

        float mn = fmaxf(m, d);
        float r  = expf(m - mn);         // first iter: expf(-inf)=0 -> clean start
        float e  = expf(d - mn);
        ss = ss * r + e;
        a0.x = a0.x*r + e*v0.x;  a0.y = a0.y*r + e*v0.y;
        a0.z = a0.z*r + e*v0.z;  a0.w = a0.w*r + e*v0.w;
        a1.x = a1.x*r + e*v1.x;  a1.y = a1.y*r + e*v1.y;
        a1.z = a1.z*r + e*v1.z;  a1.w = a1.w*r + e*v1.w;
        m = mn;
    }

    // Cross-warp merge.
    if (l == 0) s_m[w] = m;
    __syncthreads();
    float M = s_m[0];
    #pragma unroll
    for (int k = 1; k < 8; ++k) M = fmaxf(M, s_m[k]);   // finite (segment nonempty)

    float r = expf(m - M);               // warp with no nodes: expf(-inf)=0
    ss *= r;
    if (l == 0) s_s[w] = ss;
    s_acc[w][l*8+0] = a0.x*r; s_acc[w][l*8+1] = a0.y*r;
    s_acc[w][l*8+2] = a0.z*r; s_acc[w][l*8+3] = a0.w*r;
    s_acc[w][l*8+4] = a1.x*r; s_acc[w][l*8+5] = a1.y*r;
    s_acc[w][l*8+6] = a1.z*r; s_acc[w][l*8+7] = a1.w*r;
    __syncthreads();

    const float denom = s_s[0]+s_s[1]+s_s[2]+s_s[3]+s_s[4]+s_s[5]+s_s[6]+s_s[7];
    const float scale = 1.f / (denom + 1e-16f);

    float p = 0.f;
    #pragma unroll
    for (int k = 0; k < 8; ++k) p += s_acc[k][tid];
    g_pool[(size_t)b * FDIM + tid] = p * scale;
    if (tid == 0) g_gsum[b] = denom * scale;

    // Normalize stashed logits into final gate values.
    for (int i = start + tid; i < end; i += 256)
        gate[i] = expf(gate[i] - M) * scale;
}

// Kernel 2: out[512,256] = g_pool @ Wnn + g_gsum ⊗ bnn.  64 blocks x 8 rows
// keeps Wnn L2 traffic at 16 MB instead of 128 MB.
__global__ __launch_bounds__(256) void gemm_kernel(
    const float* __restrict__ Wnn, const float* __restrict__ bnn,
    float* __restrict__ out)
{
    const int rb = blockIdx.x * ROWS;
    const int t  = threadIdx.x;

    __shared__ float s_p[ROWS][FDIM];
    __shared__ float s_g[ROWS];
    #pragma unroll
    for (int r = 0; r < ROWS; ++r) s_p[r][t] = g_pool[(size_t)(rb + r) * FDIM + t];
    if (t < ROWS) s_g[t] = g_gsum[rb + t];
    __syncthreads();

    float acc[ROWS];
    #pragma unroll
    for (int r = 0; r < ROWS; ++r) acc[r] = 0.f;

    #pragma unroll 4
    for (int k = 0; k < FDIM; ++k) {
        float wv = Wnn[(size_t)k * FDIM + t];
        #pragma unroll
        for (int r = 0; r < ROWS; ++r) acc[r] += s_p[r][k] * wv;
    }

    const float bv = bnn[t];
    #pragma unroll
    for (int r = 0; r < ROWS; ++r)
        out[(size_t)(rb + r) * FDIM + t] = acc[r] + bv * s_g[r];
}

extern "C" void kernel_launch(void* const* d_in, const int* in_sizes, int n_in,
                              void* d_out, int out_size) {
    // Identify inputs by size (robust to presence/absence of the scalar `size`):
    // x = largest; batch has N = |x|/256 elements; W_nn = 65536; among 256-sized
    // tensors W_gate comes first (metadata order), b_nn second; b_gate follows W_gate.
    int ix = 0;
    for (int i = 1; i < n_in; i++) if (in_sizes[i] > in_sizes[ix]) ix = i;
    const int N = in_sizes[ix] / FDIM;

    int ib = -1, iwn = -1, iwg = -1, ibn = -1;
    for (int i = 0; i < n_in; i++) {
        if (i == ix) continue;
        if (in_sizes[i] == N) ib = i;
        else if (in_sizes[i] == FDIM * FDIM) iwn = i;
        else if (in_sizes[i] == FDIM) { if (iwg < 0) iwg = i; else ibn = i; }
    }
    const int ibg = iwg + 1;  // b_gate immediately follows W_gate

    const float* x   = (const float*)d_in[ix];
    const int*   bt  = (const int*)  d_in[ib];
    const float* Wg  = (const float*)d_in[iwg];
    const float* bg  = (const float*)d_in[ibg];
    const float* Wnn = (const float*)d_in[iwn];
    const float* bnn = (const float*)d_in[ibn];

    float* out  = (float*)d_out;             // [512, 256]
    float* gate = out + SGRAPHS * FDIM;      // [N, 1]

    pool_kernel<<<SGRAPHS, 256>>>(x, bt, N, Wg, bg, gate);
    gemm_kernel<<<SGRAPHS / ROWS, 256>>>(Wnn, bnn, out);
}

// round 4
// speedup vs baseline: 1.4657x; 1.4657x over previous
#include <cuda_runtime.h>
#include <math_constants.h>

#define FDIM 256
#define SGRAPHS 512
#define GROWS 4          // graphs per block in the GEMM kernel

__device__ float g_pool[SGRAPHS * FDIM];   // zero at load; empty segments stay 0
__device__ float g_gsum[SGRAPHS];

__device__ __forceinline__ int lowerb(const int* __restrict__ a, int n, int v) {
    int lo = 0, hi = n;
    while (lo < hi) { int m = (lo + hi) >> 1; if (a[m] < v) lo = m + 1; else hi = m; }
    return lo;
}

// Kernel 1: one block per graph. Single pass over x with online softmax-weighted
// accumulation; TWO independent chains per warp for ILP across the serial
// shfl+exp+rescale dependency. Writes gate[N], g_pool[b][:], g_gsum[b].
__global__ __launch_bounds__(256) void pool_kernel(
    const float* __restrict__ x, const int* __restrict__ batch, int n_nodes,
    const float* __restrict__ Wg, const float* __restrict__ bg,
    float* __restrict__ gate)
{
    const int b   = blockIdx.x;
    const int tid = threadIdx.x;
    const int w   = tid >> 5, l = tid & 31;

    __shared__ int   s_b[2];
    __shared__ float s_m[8], s_s[8];
    __shared__ float s_acc[8][FDIM];

    if (tid == 0) {
        s_b[0] = lowerb(batch, n_nodes, b);
        s_b[1] = lowerb(batch, n_nodes, b + 1);
    }
    __syncthreads();
    const int start = s_b[0], end = s_b[1];
    if (end == start) return;            // g_pool/g_gsum stay zero -> out row = 0

    const float4 wg0 = *(const float4*)(Wg + l * 8);
    const float4 wg1 = *(const float4*)(Wg + l * 8 + 4);
    const float  bgv = bg[0];

    // Two independent online chains (even/odd warp-slots).
    float  m0 = -CUDART_INF_F, ss0 = 0.f;
    float  m1 = -CUDART_INF_F, ss1 = 0.f;
    float4 p00 = make_float4(0,0,0,0), p01 = make_float4(0,0,0,0);
    float4 p10 = make_float4(0,0,0,0), p11 = make_float4(0,0,0,0);

    for (int i = start + w; i < end; i += 16) {
        // ---- chain 0: node i ----
        const float4* xr0 = (const float4*)(x + (size_t)i * FDIM);
        float4 u0 = xr0[l * 2];
        float4 u1 = xr0[l * 2 + 1];
        float d0 = u0.x*wg0.x + u0.y*wg0.y + u0.z*wg0.z + u0.w*wg0.w
                 + u1.x*wg1.x + u1.y*wg1.y + u1.z*wg1.z + u1.w*wg1.w;

        // ---- chain 1: node i+8 (may not exist) ----
        const int j = i + 8;
        const bool has1 = (j < end);
        const float4* xr1 = (const float4*)(x + (size_t)(has1 ? j : i) * FDIM);
        float4 v0 = xr1[l * 2];
        float4 v1 = xr1[l * 2 + 1];
        float d1 = v0.x*wg0.x + v0.y*wg0.y + v0.z*wg0.z + v0.w*wg0.w
                 + v1.x*wg1.x + v1.y*wg1.y + v1.z*wg1.z + v1.w*wg1.w;

        #pragma unroll
        for (int o = 16; o; o >>= 1) {
            d0 += __shfl_xor_sync(0xffffffffu, d0, o);
            d1 += __shfl_xor_sync(0xffffffffu, d1, o);
        }
        d0 += bgv;  d1 += bgv;
        if (l == 0) gate[i] = d0;
        if (has1 && l == 1) gate[j] = d1;

        {   // chain 0 update
            float mn = fmaxf(m0, d0);
            float r  = expf(m0 - mn);
            float e  = expf(d0 - mn);
            ss0 = ss0 * r + e;
            p00.x = p00.x*r + e*u0.x;  p00.y = p00.y*r + e*u0.y;
            p00.z = p00.z*r + e*u0.z;  p00.w = p00.w*r + e*u0.w;
            p01.x = p01.x*r + e*u1.x;  p01.y = p01.y*r + e*u1.y;
            p01.z = p01.z*r + e*u1.z;  p01.w = p01.w*r + e*u1.w;
            m0 = mn;
        }
        if (has1) {  // chain 1 update
            float mn = fmaxf(m1, d1);
            float r  = expf(m1 - mn);
            float e  = expf(d1 - mn);
            ss1 = ss1 * r + e;
            p10.x = p10.x*r + e*v0.x;  p10.y = p10.y*r + e*v0.y;
            p10.z = p10.z*r + e*v0.z;  p10.w = p10.w*r + e*v0.w;
            p11.x = p11.x*r + e*v1.x;  p11.y = p11.y*r + e*v1.y;
            p11.z = p11.z*r + e*v1.z;  p11.w = p11.w*r + e*v1.w;
            m1 = mn;
        }
    }

    // Cross-warp + cross-chain merge against the global block max M (finite,
    // since the segment is nonempty). Empty chains have m=-inf -> weight 0.
    if (l == 0) s_m[w] = fmaxf(m0, m1);
    __syncthreads();
    float M = s_m[0];
    #pragma unroll
    for (int k = 1; k < 8; ++k) M = fmaxf(M, s_m[k]);

    const float r0 = expf(m0 - M);
    const float r1 = expf(m1 - M);
    if (l == 0) s_s[w] = ss0 * r0 + ss1 * r1;
    s_acc[w][l*8+0] = p00.x*r0 + p10.x*r1;  s_acc[w][l*8+1] = p00.y*r0 + p10.y*r1;
    s_acc[w][l*8+2] = p00.z*r0 + p10.z*r1;  s_acc[w][l*8+3] = p00.w*r0 + p10.w*r1;
    s_acc[w][l*8+4] = p01.x*r0 + p11.x*r1;  s_acc[w][l*8+5] = p01.y*r0 + p11.y*r1;
    s_acc[w][l*8+6] = p01.z*r0 + p11.z*r1;  s_acc[w][l*8+7] = p01.w*r0 + p11.w*r1;
    __syncthreads();

    const float denom = s_s[0]+s_s[1]+s_s[2]+s_s[3]+s_s[4]+s_s[5]+s_s[6]+s_s[7];
    const float scale = 1.f / (denom + 1e-16f);

    float p = 0.f;
    #pragma unroll
    for (int k = 0; k < 8; ++k) p += s_acc[k][tid];
    g_pool[(size_t)b * FDIM + tid] = p * scale;
    if (tid == 0) g_gsum[b] = denom * scale;

    // Normalize stashed logits into final gate values.
    for (int i = start + tid; i < end; i += 256)
        gate[i] = expf(gate[i] - M) * scale;
}

// Kernel 2: out[512,256] = g_pool @ Wnn + g_gsum ⊗ bnn.
// 128 blocks x 4 rows; float4 Wnn loads; 4-way k-split + smem reduce.
__global__ __launch_bounds__(256) void gemm_kernel(
    const float* __restrict__ Wnn, const float* __restrict__ bnn,
    float* __restrict__ out)
{
    const int rb = blockIdx.x * GROWS;
    const int t  = threadIdx.x;
    const int c4 = t & 63;     // float4 column group (0..63)
    const int kp = t >> 6;     // k partition (0..3)

    __shared__ float  s_p[GROWS][FDIM];
    __shared__ float  s_g[GROWS];
    __shared__ float4 s_red[4][GROWS][64];

    #pragma unroll
    for (int j = t; j < GROWS * FDIM; j += 256)
        s_p[j >> 8][j & 255] = g_pool[(size_t)rb * FDIM + j];
    if (t < GROWS) s_g[t] = g_gsum[rb + t];
    __syncthreads();

    float4 acc[GROWS];
    #pragma unroll
    for (int r = 0; r < GROWS; ++r) acc[r] = make_float4(0,0,0,0);

    const int k0 = kp * 64;
    #pragma unroll 8
    for (int kk = 0; kk < 64; ++kk) {
        const int k = k0 + kk;
        float4 wv = *(const float4*)(Wnn + (size_t)k * FDIM + c4 * 4);
        #pragma unroll
        for (int r = 0; r < GROWS; ++r) {
            float p = s_p[r][k];
            acc[r].x += p * wv.x;  acc[r].y += p * wv.y;
            acc[r].z += p * wv.z;  acc[r].w += p * wv.w;
        }
    }
    #pragma unroll
    for (int r = 0; r < GROWS; ++r) s_red[kp][r][c4] = acc[r];
    __syncthreads();

    // 256 threads = 4 rows x 64 col-quads: finalize one float4 each.
    const int r = t >> 6, c = t & 63;
    float4 o0 = s_red[0][r][c], o1 = s_red[1][r][c];
    float4 o2 = s_red[2][r][c], o3 = s_red[3][r][c];
    float4 bv = *(const float4*)(bnn + c * 4);
    const float gs = s_g[r];
    float4 res;
    res.x = o0.x + o1.x + o2.x + o3.x + bv.x * gs;
    res.y = o0.y + o1.y + o2.y + o3.y + bv.y * gs;
    res.z = o0.z + o1.z + o2.z + o3.z + bv.z * gs;
    res.w = o0.w + o1.w + o2.w + o3.w + bv.w * gs;
    *(float4*)(out + (size_t)(rb + r) * FDIM + c * 4) = res;
}

extern "C" void kernel_launch(void* const* d_in, const int* in_sizes, int n_in,
                              void* d_out, int out_size) {
    // x = largest; batch has N = |x|/256 elements; W_nn = 65536; among 256-sized
    // tensors W_gate comes first (metadata order), b_nn second; b_gate follows W_gate.
    int ix = 0;
    for (int i = 1; i < n_in; i++) if (in_sizes[i] > in_sizes[ix]) ix = i;
    const int N = in_sizes[ix] / FDIM;

    int ib = -1, iwn = -1, iwg = -1, ibn = -1;
    for (int i = 0; i < n_in; i++) {
        if (i == ix) continue;
        if (in_sizes[i] == N) ib = i;
        else if (in_sizes[i] == FDIM * FDIM) iwn = i;
        else if (in_sizes[i] == FDIM) { if (iwg < 0) iwg = i; else ibn = i; }
    }
    const int ibg = iwg + 1;  // b_gate immediately follows W_gate

    const float* x   = (const float*)d_in[ix];
    const int*   bt  = (const int*)  d_in[ib];
    const float* Wg  = (const float*)d_in[iwg];
    const float* bg  = (const float*)d_in[ibg];
    const float* Wnn = (const float*)d_in[iwn];
    const float* bnn = (const float*)d_in[ibn];

    float* out  = (float*)d_out;             // [512, 256]
    float* gate = out + SGRAPHS * FDIM;      // [N, 1]

    pool_kernel<<<SGRAPHS, 256>>>(x, bt, N, Wg, bg, gate);
    gemm_kernel<<<SGRAPHS / GROWS, 256>>>(Wnn, bnn, out);
}